// round 1
// baseline (speedup 1.0000x reference)
#include <cuda_runtime.h>
#include <math.h>

#define NB 256
#define NI 1152
#define NJ 10
#define NDIN 8
#define NDOUT 16
#define NJD (NJ*NDOUT)           /* 160 */
#define XSTRIDE (NI*NDIN)        /* 9216 */
#define WSTRIDE (NJ*NDOUT*NDIN)  /* 1280 */

__device__ float g_logits[NI*NJ];
__device__ float g_c[NI*NJ];
__device__ float g_s[NB*NJD];

__global__ void k_zero() {
    int idx = blockIdx.x*256 + threadIdx.x;
    if (idx < NI*NJ) g_logits[idx] = 0.f;
}

__global__ void k_softmax() {
    int i = blockIdx.x*128 + threadIdx.x;
    if (i >= NI) return;
    float v[NJ];
    float m = -1e30f;
#pragma unroll
    for (int j = 0; j < NJ; j++) { v[j] = g_logits[i*NJ+j]; m = fmaxf(m, v[j]); }
    float ssum = 0.f;
#pragma unroll
    for (int j = 0; j < NJ; j++) { v[j] = expf(v[j]-m); ssum += v[j]; }
    float inv = 1.f/ssum;
#pragma unroll
    for (int j = 0; j < NJ; j++) g_c[i*NJ+j] = v[j]*inv;
}

/* ------------------------------------------------------------------ */
/* s kernel: s[b,j,d] = sum_{i,d'} x[b,i,d'] * (c[i,j]*W[i,j,d,d'])   */
/* grid (J=10, 32 b-tiles of 8), block 128 = 16 k-slices x 8 out-thr  */
/* thread tile: 4 b (stride 2) x 4 d (stride 4) = 16 accumulators     */
/* squash fused in epilogue; deterministic fixed-order reductions.    */
/* ------------------------------------------------------------------ */
#define SBX 388                  /* padded b-stride in x smem (floats) */
#define XS_SIZE (8*SBX)          /* 3104 */
#define WOFF XS_SIZE
#define SIW 132                  /* padded i-stride in W smem */
#define SM_SIZE (XS_SIZE + 32*SIW)  /* 3104 + 4224 = 7328 floats */

__global__ __launch_bounds__(128) void k_s(const float* __restrict__ x,
                                           const float* __restrict__ W,
                                           float* __restrict__ outp, int to_out) {
    __shared__ float sm[SM_SIZE];
    const int j   = blockIdx.x;
    const int b0  = blockIdx.y * 8;
    const int tid = threadIdx.x;
    const int ks  = tid >> 3;      /* 0..15 k-slice */
    const int ot  = tid & 7;
    const int bg  = ot >> 2;       /* 0..1 */
    const int dg  = ot & 3;        /* 0..3 */

    float acc[4][4];
#pragma unroll
    for (int r = 0; r < 4; r++)
#pragma unroll
        for (int r2 = 0; r2 < 4; r2++) acc[r][r2] = 0.f;

    for (int ch = 0; ch < 36; ch++) {
        const int i0 = ch*32;
        /* stage Wc = c[i,j]*W[i,j,:,:]  (32 i x 128 floats) */
        for (int idx = tid; idx < 1024; idx += 128) {
            int il = idx >> 5;
            int r  = idx & 31;
            float c = g_c[(i0+il)*NJ + j];
            float4 w = *(const float4*)(W + (size_t)(i0+il)*WSTRIDE + j*128 + r*4);
            w.x *= c; w.y *= c; w.z *= c; w.w *= c;
            *(float4*)(sm + WOFF + il*SIW + r*4) = w;
        }
        /* stage x tile (8 b x 32 i x 8 d') */
        for (int idx = tid; idx < 512; idx += 128) {
            int bl = idx >> 6;
            int k  = idx & 63;
            float4 v = *(const float4*)(x + (size_t)(b0+bl)*XSTRIDE + i0*NDIN + k*4);
            int il = k >> 1, h = k & 1;
            *(float4*)(sm + bl*SBX + il*12 + h*4) = v;
        }
        __syncthreads();

#pragma unroll
        for (int ii = 0; ii < 2; ii++) {
            const int il = ks*2 + ii;
            float4 xa[4][2];
#pragma unroll
            for (int r = 0; r < 4; r++) {
                int bl = bg + 2*r;
                xa[r][0] = *(const float4*)(sm + bl*SBX + il*12);
                xa[r][1] = *(const float4*)(sm + bl*SBX + il*12 + 4);
            }
#pragma unroll
            for (int r2 = 0; r2 < 4; r2++) {
                const int d = dg + 4*r2;
                float4 w0 = *(const float4*)(sm + WOFF + il*SIW + d*8);
                float4 w1 = *(const float4*)(sm + WOFF + il*SIW + d*8 + 4);
#pragma unroll
                for (int r = 0; r < 4; r++) {
                    acc[r][r2] += xa[r][0].x*w0.x + xa[r][0].y*w0.y
                                + xa[r][0].z*w0.z + xa[r][0].w*w0.w
                                + xa[r][1].x*w1.x + xa[r][1].y*w1.y
                                + xa[r][1].z*w1.z + xa[r][1].w*w1.w;
                }
            }
        }
        __syncthreads();
    }

    /* reduce the 16 k-slices (fixed order) */
#pragma unroll
    for (int r = 0; r < 4; r++)
#pragma unroll
        for (int r2 = 0; r2 < 4; r2++) {
            int outidx = (bg + 2*r)*16 + (dg + 4*r2);
            sm[outidx*16 + ks] = acc[r][r2];
        }
    __syncthreads();

    const int bl = tid >> 4, d = tid & 15;
    float v = 0.f;
#pragma unroll
    for (int k = 0; k < 16; k++) v += sm[tid*16 + k];
    sm[2048 + tid] = v;
    __syncthreads();

    /* squash over the 16 d of this (b, j) */
    float ss = 0.f;
#pragma unroll
    for (int dd = 0; dd < 16; dd++) { float t = sm[2048 + bl*16 + dd]; ss += t*t; }
    float l2 = sqrtf(ss);
    float f  = l2 / (1.f + ss);      /* |s|/(1+|s|^2) */
    float val = v * f;
    size_t o = (size_t)(b0+bl)*NJD + j*16 + d;
    if (to_out) outp[o] = val; else g_s[o] = val;
}

/* ------------------------------------------------------------------ */
/* agreement: b[i,j] += sum_{d,d'} W[i,j,d,d'] * (sum_b x[b,i,d']*s[b,j,d]) */
/* grid 288 (4 i each), block 128 = 4 warps (warp <-> i), lane owns 5 jd */
/* ------------------------------------------------------------------ */
__global__ __launch_bounds__(128) void k_agree(const float* __restrict__ x,
                                               const float* __restrict__ W) {
    __shared__ float sm[6144];     /* x: [0,1024) ; s: [1024,6144) ; A reuses all */
    const int i0   = blockIdx.x * 4;
    const int tid  = threadIdx.x;
    const int il   = tid >> 5;
    const int lane = tid & 31;

    float a[8][5];
#pragma unroll
    for (int dp = 0; dp < 8; dp++)
#pragma unroll
        for (int k = 0; k < 5; k++) a[dp][k] = 0.f;

    for (int bc = 0; bc < 8; bc++) {
        for (int idx = tid; idx < 256; idx += 128) {
            int bl = idx >> 3, k = idx & 7;
            *(float4*)(sm + bl*32 + k*4) =
                *(const float4*)(x + (size_t)(bc*32+bl)*XSTRIDE + i0*NDIN + k*4);
        }
        for (int idx = tid; idx < 1280; idx += 128) {
            int bl = idx/40, k = idx - bl*40;
            *(float4*)(sm + 1024 + bl*160 + k*4) =
                *(const float4*)(g_s + (size_t)(bc*32+bl)*NJD + k*4);
        }
        __syncthreads();

        for (int bl = 0; bl < 32; bl++) {
            float4 xv0 = *(const float4*)(sm + bl*32 + il*8);
            float4 xv1 = *(const float4*)(sm + bl*32 + il*8 + 4);
            const float* sp = sm + 1024 + bl*160 + lane*5;
#pragma unroll
            for (int k = 0; k < 5; k++) {
                float s0 = sp[k];
                a[0][k] += xv0.x*s0; a[1][k] += xv0.y*s0;
                a[2][k] += xv0.z*s0; a[3][k] += xv0.w*s0;
                a[4][k] += xv1.x*s0; a[5][k] += xv1.y*s0;
                a[6][k] += xv1.z*s0; a[7][k] += xv1.w*s0;
            }
        }
        __syncthreads();
    }

    /* dump A_i[d', jd] to shared as [il][jd][d'] */
#pragma unroll
    for (int dp = 0; dp < 8; dp++)
#pragma unroll
        for (int k = 0; k < 5; k++)
            sm[il*1280 + (lane*5+k)*8 + dp] = a[dp][k];
    __syncthreads();

    if (tid < 40) {
        int iloc = tid/10, jj = tid - iloc*10;
        int i = i0 + iloc;
        const float* Wi = W  + (size_t)i*WSTRIDE + jj*128;
        const float* Ai = sm + iloc*1280 + jj*128;
        float accv = 0.f;
#pragma unroll
        for (int t = 0; t < 32; t++) {
            float4 wv = *(const float4*)(Wi + t*4);
            float4 av = *(const float4*)(Ai + t*4);
            accv += wv.x*av.x + wv.y*av.y + wv.z*av.z + wv.w*av.w;
        }
        g_logits[i*NJ + jj] += accv;
    }
}

extern "C" void kernel_launch(void* const* d_in, const int* in_sizes, int n_in,
                              void* d_out, int out_size) {
    const float* x = (const float*)d_in[0];
    const float* W = (const float*)d_in[1];
    float* out = (float*)d_out;

    k_zero<<<45, 256>>>();
    for (int it = 0; it < 3; it++) {
        k_softmax<<<9, 128>>>();
        k_s<<<dim3(NJ, 32), 128>>>(x, W, out, (it == 2) ? 1 : 0);
        if (it < 2) k_agree<<<288, 128>>>(x, W);   /* iter-3 logit update is dead code */
    }
}

// round 4
// speedup vs baseline: 1.4066x; 1.4066x over previous
#include <cuda_runtime.h>
#include <math.h>

#define NB 256
#define NI 1152
#define NJ 10
#define NJD 160
#define XSTR 9216
#define WSTR 1280

typedef unsigned long long u64;

__device__ float g_logits[NI*NJ];
__device__ float g_c[NI*NJ];
__device__ float g_s[NB*NJD];
__device__ float g_part[2][NB*NJD];
__device__ float g_pl[2][NI*NJ];
__device__ float g_Wt[NI*WSTR];

__device__ __forceinline__ void fma2(u64& d, u64 a, u64 b) {
    asm("fma.rn.f32x2 %0, %1, %2, %0;" : "+l"(d) : "l"(a), "l"(b));
}

__global__ void k_zero() {
    int idx = blockIdx.x*256 + threadIdx.x;
    if (idx < NI*NJ) g_logits[idx] = 0.f;
}

/* pre-transpose W -> Wt[i][j][d'][d] (iteration-invariant) */
__global__ void k_wt(const float* __restrict__ W) {
    int idx = blockIdx.x*256 + threadIdx.x;
    if (idx >= NI*WSTR) return;
    int r  = idx & 127;
    int ij = idx >> 7;
    int d = r & 15, dp = r >> 4;
    g_Wt[idx] = W[(ij << 7) + d*8 + dp];
}

__global__ void k_softmax(int add) {
    int i = blockIdx.x*128 + threadIdx.x;
    if (i >= NI) return;
    float v[NJ];
    float m = -1e30f;
#pragma unroll
    for (int j = 0; j < NJ; j++) {
        float l = g_logits[i*NJ+j];
        if (add) {
            l += g_pl[0][i*NJ+j] + g_pl[1][i*NJ+j];
            g_logits[i*NJ+j] = l;
        }
        v[j] = l; m = fmaxf(m, l);
    }
    float ssum = 0.f;
#pragma unroll
    for (int j = 0; j < NJ; j++) { v[j] = expf(v[j]-m); ssum += v[j]; }
    float inv = 1.f/ssum;
#pragma unroll
    for (int j = 0; j < NJ; j++) g_c[i*NJ+j] = v[j]*inv;
}

/* ------------------------------------------------------------------ */
/* k_s: partial s[b,j,d] = sum_{i in half, d'} (c*x)[b,i,d']*W[i,j,d,d'] */
/* grid (10, 32, 2) x 128 thr.  tid: ks=i-slice(32), bg(2), dg(2).     */
/* thread tile 4b x 8d, f32x2 packed along d; x pre-dup'd (c folded).  */
/* ------------------------------------------------------------------ */
#define SW 132
#define WOFF 0
#define XOFF 4224

__global__ __launch_bounds__(128,5) void k_s(const float* __restrict__ x) {
    __shared__ __align__(16) float sm[8448];
    const int j = blockIdx.x, b0 = blockIdx.y*8, half = blockIdx.z;
    const int tid = threadIdx.x;
    const int ks = tid >> 2, ot = tid & 3, bg = ot >> 1, dg = ot & 1;

    u64 acc[4][4];
#pragma unroll
    for (int r = 0; r < 4; r++)
#pragma unroll
        for (int p = 0; p < 4; p++) acc[r][p] = 0ull;

    for (int ch = 0; ch < 18; ch++) {
        const int i0 = half*576 + ch*32;
        /* stage Wt tile: 32 i x 128 floats (pure copy, pre-transposed) */
#pragma unroll
        for (int t = 0; t < 8; t++) {
            int q = tid + t*128;
            int il = q >> 5, r = q & 31;
            float4 w = *(const float4*)(g_Wt + (size_t)(i0+il)*WSTR + j*128 + r*4);
            *(float4*)(sm + WOFF + il*SW + r*4) = w;
        }
        /* stage x dup'd + scaled by c[i,j]: layout [il][bl*16 + dp*2] */
#pragma unroll
        for (int t = 0; t < 4; t++) {
            int q = tid + t*128;
            int bl = q >> 6, k = q & 63;
            int il = k >> 1, h = k & 1;
            float4 v = *(const float4*)(x + (size_t)(b0+bl)*XSTR + i0*8 + k*4);
            float c = g_c[(i0+il)*NJ + j];
            float4 d0 = make_float4(v.x*c, v.x*c, v.y*c, v.y*c);
            float4 d1 = make_float4(v.z*c, v.z*c, v.w*c, v.w*c);
            *(float4*)(sm + XOFF + il*SW + bl*16 + h*8)     = d0;
            *(float4*)(sm + XOFF + il*SW + bl*16 + h*8 + 4) = d1;
        }
        __syncthreads();

        const float* wp = sm + WOFF + ks*SW + dg*8;
        const float* xp = sm + XOFF + ks*SW + bg*16;
#pragma unroll
        for (int h = 0; h < 2; h++) {
            u64 w[16];
#pragma unroll
            for (int dp2 = 0; dp2 < 4; dp2++) {
                ulonglong2 t0 = *(const ulonglong2*)(wp + (h*4+dp2)*16);
                ulonglong2 t1 = *(const ulonglong2*)(wp + (h*4+dp2)*16 + 4);
                w[dp2*4+0] = t0.x; w[dp2*4+1] = t0.y;
                w[dp2*4+2] = t1.x; w[dp2*4+3] = t1.y;
            }
#pragma unroll
            for (int r = 0; r < 4; r++) {
                ulonglong2 x0 = *(const ulonglong2*)(xp + r*32 + h*8);
                ulonglong2 x1 = *(const ulonglong2*)(xp + r*32 + h*8 + 4);
                u64 xv[4] = {x0.x, x0.y, x1.x, x1.y};
#pragma unroll
                for (int dp2 = 0; dp2 < 4; dp2++)
#pragma unroll
                    for (int p = 0; p < 4; p++)
                        fma2(acc[r][p], xv[dp2], w[dp2*4+p]);
            }
        }
        __syncthreads();
    }

    /* reduce 32 k-slices via smem (pad 33 -> conflict-free) */
#pragma unroll
    for (int r = 0; r < 4; r++)
#pragma unroll
        for (int p = 0; p < 4; p++) {
            float2 f = *(float2*)&acc[r][p];
            int outl = (bg + 2*r)*16 + dg*8 + 2*p;
            sm[outl*33 + ks]     = f.x;
            sm[(outl+1)*33 + ks] = f.y;
        }
    __syncthreads();
    float v = 0.f;
#pragma unroll
    for (int k2 = 0; k2 < 32; k2++) v += sm[tid*33 + k2];
    int bl = tid >> 4, d = tid & 15;
    g_part[half][(size_t)(b0+bl)*NJD + j*16 + d] = v;
}

/* combine K-split halves + squash */
__global__ void k_squash(float* __restrict__ outp, int to_out) {
    int tid = threadIdx.x;
    int g = tid >> 4, d = tid & 15;
    int bj = blockIdx.x*16 + g;
    int b = bj/10, j = bj - b*10;
    int idx = b*NJD + j*16 + d;
    float v = g_part[0][idx] + g_part[1][idx];
    float ss = v*v;
    ss += __shfl_xor_sync(~0u, ss, 1);
    ss += __shfl_xor_sync(~0u, ss, 2);
    ss += __shfl_xor_sync(~0u, ss, 4);
    ss += __shfl_xor_sync(~0u, ss, 8);
    float f = sqrtf(ss)/(1.f + ss);
    float r = v*f;
    if (to_out) outp[idx] = r; else g_s[idx] = r;
}

/* ------------------------------------------------------------------ */
/* k_agree: pl[half][i,j] = sum_{d,d'} W[i,j,d,d'] * A[i,d',j,d],      */
/* A = sum_{b in half} x[b,i,d'] s[b,j,d].  grid (288, 2) x 128 thr.   */
/* warp<->i (4/block), lane<->jd (stride-32), f32x2 packed along d'.   */
/* ------------------------------------------------------------------ */
#define A_XOFF 0
#define A_SOFF 1024

__global__ __launch_bounds__(128,4) void k_agree(const float* __restrict__ x,
                                                 const float* __restrict__ W) {
    __shared__ __align__(16) float sm[11264];
    const int i0 = blockIdx.x*4;
    const int half = blockIdx.y;
    const int tid = threadIdx.x, il = tid >> 5, lane = tid & 31;

    u64 a[4][5];
#pragma unroll
    for (int dp2 = 0; dp2 < 4; dp2++)
#pragma unroll
        for (int k = 0; k < 5; k++) a[dp2][k] = 0ull;

    for (int bc = 0; bc < 4; bc++) {
        const int bb = half*128 + bc*32;
        /* stage x: 32 b x (4 i x 8 d') */
#pragma unroll
        for (int t = 0; t < 2; t++) {
            int q = tid + t*128;
            int bl = q >> 3, k = q & 7;
            *(float4*)(sm + A_XOFF + bl*32 + k*4) =
                *(const float4*)(x + (size_t)(bb+bl)*XSTR + i0*8 + k*4);
        }
        /* stage s dup'd: [bl][jd*2 + {0,1}] — FULL 160 jd per b (fixed) */
#pragma unroll
        for (int t = 0; t < 20; t++) {
            int q = tid + t*128;           /* 0..2559 */
            int bl = q/80, m = q - bl*80;  /* bl 0..31, m 0..79 */
            float2 sv = *(const float2*)(g_s + (size_t)(bb+bl)*NJD + m*2);
            *(float4*)(sm + A_SOFF + bl*320 + m*4) = make_float4(sv.x, sv.x, sv.y, sv.y);
        }
        __syncthreads();

#pragma unroll 4
        for (int bl = 0; bl < 32; bl++) {
            const float* xp = sm + A_XOFF + bl*32 + il*8;
            ulonglong2 x0 = *(const ulonglong2*)(xp);
            ulonglong2 x1 = *(const ulonglong2*)(xp + 4);
            u64 xv[4] = {x0.x, x0.y, x1.x, x1.y};
            const float* sp = sm + A_SOFF + bl*320;
#pragma unroll
            for (int k = 0; k < 5; k++) {
                u64 sv = *(const u64*)(sp + (lane + 32*k)*2);
#pragma unroll
                for (int dp2 = 0; dp2 < 4; dp2++) fma2(a[dp2][k], xv[dp2], sv);
            }
        }
        __syncthreads();
    }

    /* dump A as [il][j][d][d'] (matches W inner layout) */
#pragma unroll
    for (int dp2 = 0; dp2 < 4; dp2++)
#pragma unroll
        for (int k = 0; k < 5; k++)
            *(u64*)(sm + il*1280 + (lane + 32*k)*8 + dp2*2) = a[dp2][k];
    __syncthreads();

    if (tid < 40) {
        int iloc = tid/10, jj = tid - iloc*10;
        int i = i0 + iloc;
        const float* Wi = W  + (size_t)i*WSTR + jj*128;
        const float* Ai = sm + iloc*1280 + jj*128;
        float accv = 0.f;
#pragma unroll
        for (int t = 0; t < 32; t++) {
            float4 wv = *(const float4*)(Wi + t*4);
            float4 av = *(const float4*)(Ai + t*4);
            accv += wv.x*av.x + wv.y*av.y + wv.z*av.z + wv.w*av.w;
        }
        g_pl[half][i*NJ + jj] = accv;
    }
}

extern "C" void kernel_launch(void* const* d_in, const int* in_sizes, int n_in,
                              void* d_out, int out_size) {
    const float* x = (const float*)d_in[0];
    const float* W = (const float*)d_in[1];
    float* out = (float*)d_out;

    k_wt<<<5760, 256>>>(W);
    k_zero<<<45, 256>>>();
    for (int it = 0; it < 3; it++) {
        k_softmax<<<9, 128>>>(it ? 1 : 0);
        k_s<<<dim3(NJ, 32, 2), 128>>>(x);
        k_squash<<<160, 256>>>(out, (it == 2) ? 1 : 0);
        if (it < 2) k_agree<<<dim3(288, 2), 128>>>(x, W);
    }
}

// round 6
// speedup vs baseline: 2.3209x; 1.6500x over previous
#include <cuda_runtime.h>
#include <cuda_bf16.h>
#include <math.h>
#include <stdint.h>

#define NB 256
#define NI 1152
#define NJ 10
#define NJD 160
#define XSTR 9216
#define WSTR 1280
#define KSPLIT 72
#define KRANGE 128

typedef unsigned long long u64;

__device__ float g_logits[NI*NJ];
__device__ float g_c[NI*NJ];
__device__ float g_s[NB*NJD];
__device__ float g_pl[2][NI*NJ];
__device__ float g_pp[KSPLIT*NB*NJD];
__device__ __nv_bfloat16 g_xhi[NB*XSTR];
__device__ __nv_bfloat16 g_xlo[NB*XSTR];
__device__ __nv_bfloat16 g_whi[NJD*XSTR];
__device__ __nv_bfloat16 g_wlo[NJD*XSTR];

__device__ __forceinline__ void fma2(u64& d, u64 a, u64 b) {
    asm("fma.rn.f32x2 %0, %1, %2, %0;" : "+l"(d) : "l"(a), "l"(b));
}
__device__ __forceinline__ void mma16816(float* c, const unsigned* a,
                                         unsigned b0, unsigned b1) {
    asm volatile("mma.sync.aligned.m16n8k16.row.col.f32.bf16.bf16.f32 "
                 "{%0,%1,%2,%3}, {%4,%5,%6,%7}, {%8,%9}, {%0,%1,%2,%3};"
                 : "+f"(c[0]), "+f"(c[1]), "+f"(c[2]), "+f"(c[3])
                 : "r"(a[0]), "r"(a[1]), "r"(a[2]), "r"(a[3]), "r"(b0), "r"(b1));
}

__global__ void k_zero() {
    int idx = blockIdx.x*256 + threadIdx.x;
    if (idx < NI*NJ) g_logits[idx] = 0.f;
}

/* split x into bf16 hi/lo (once; layout [b][i*8+dp]) */
__global__ void k_splitx(const float* __restrict__ x) {
    int e = blockIdx.x*256 + threadIdx.x;
    float4 v = *(const float4*)(x + (size_t)e*4);
    __nv_bfloat16 h0 = __float2bfloat16_rn(v.x), h1 = __float2bfloat16_rn(v.y);
    __nv_bfloat16 h2 = __float2bfloat16_rn(v.z), h3 = __float2bfloat16_rn(v.w);
    __nv_bfloat16 l0 = __float2bfloat16_rn(v.x - __bfloat162float(h0));
    __nv_bfloat16 l1 = __float2bfloat16_rn(v.y - __bfloat162float(h1));
    __nv_bfloat16 l2 = __float2bfloat16_rn(v.z - __bfloat162float(h2));
    __nv_bfloat16 l3 = __float2bfloat16_rn(v.w - __bfloat162float(h3));
    __nv_bfloat162* ph = (__nv_bfloat162*)(g_xhi + (size_t)e*4);
    __nv_bfloat162* pl = (__nv_bfloat162*)(g_xlo + (size_t)e*4);
    ph[0] = __nv_bfloat162(h0, h1); ph[1] = __nv_bfloat162(h2, h3);
    pl[0] = __nv_bfloat162(l0, l1); pl[1] = __nv_bfloat162(l2, l3);
}

__global__ void k_softmax(int add) {
    int i = blockIdx.x*128 + threadIdx.x;
    if (i >= NI) return;
    float v[NJ];
    float m = -1e30f;
#pragma unroll
    for (int j = 0; j < NJ; j++) {
        float l = g_logits[i*NJ+j];
        if (add) {
            l += g_pl[0][i*NJ+j] + g_pl[1][i*NJ+j];
            g_logits[i*NJ+j] = l;
        }
        v[j] = l; m = fmaxf(m, l);
    }
    float ssum = 0.f;
#pragma unroll
    for (int j = 0; j < NJ; j++) { v[j] = expf(v[j]-m); ssum += v[j]; }
    float inv = 1.f/ssum;
#pragma unroll
    for (int j = 0; j < NJ; j++) g_c[i*NJ+j] = v[j]*inv;
}

/* build B = c (.) W in bf16 hi/lo: [jd][i*8+dp], jd = j*16+d */
__global__ void k_buildB(const float* __restrict__ W) {
    int e = blockIdx.x*256 + threadIdx.x;
    int jd = e / 2304;
    int q  = e - jd*2304;
    int i  = q >> 1;
    int dph = (q & 1) * 4;
    int j = jd >> 4, d = jd & 15;
    float c = g_c[i*NJ + j];
    float4 v = *(const float4*)(W + (size_t)((i*NJ + j)*16 + d)*8 + dph);
    v.x *= c; v.y *= c; v.z *= c; v.w *= c;
    __nv_bfloat16 h0 = __float2bfloat16_rn(v.x), h1 = __float2bfloat16_rn(v.y);
    __nv_bfloat16 h2 = __float2bfloat16_rn(v.z), h3 = __float2bfloat16_rn(v.w);
    __nv_bfloat16 l0 = __float2bfloat16_rn(v.x - __bfloat162float(h0));
    __nv_bfloat16 l1 = __float2bfloat16_rn(v.y - __bfloat162float(h1));
    __nv_bfloat16 l2 = __float2bfloat16_rn(v.z - __bfloat162float(h2));
    __nv_bfloat16 l3 = __float2bfloat16_rn(v.w - __bfloat162float(h3));
    size_t o = (size_t)jd*XSTR + i*8 + dph;
    __nv_bfloat162* ph = (__nv_bfloat162*)(g_whi + o);
    __nv_bfloat162* pl = (__nv_bfloat162*)(g_wlo + o);
    ph[0] = __nv_bfloat162(h0, h1); ph[1] = __nv_bfloat162(h2, h3);
    pl[0] = __nv_bfloat162(l0, l1); pl[1] = __nv_bfloat162(l2, l3);
}

/* ------------------------------------------------------------------ */
/* k_gemm (HMMA): pp[ks][b][jd] = sum_{k in ks-range} A[b,k] B[jd,k]   */
/* grid (2 mtiles, 72 ksplits) x 256 thr.  3-pass bf16 hi/lo split.    */
/* warp: 2 m16-strips x 10 n8-tiles.  Rows padded to 136 bf16.         */
/* ------------------------------------------------------------------ */
#define RS 136
#define A_HI 0
#define A_LO (128*RS)
#define B_HI (2*128*RS)
#define B_LO (2*128*RS + 160*RS)
#define GEMM_SMEM ((2*128*RS + 2*160*RS) * 2)   /* bytes = 156672 */

__global__ __launch_bounds__(256,1) void k_gemm() {
    extern __shared__ __align__(16) __nv_bfloat16 sb[];
    const int mt = blockIdx.x, ks = blockIdx.y;
    const int tid = threadIdx.x, w = tid >> 5, lane = tid & 31;
    const int g = lane >> 2, tg = lane & 3;
    const int nh = w >> 2;         /* n-half: cols 80*nh..+79 */
    const int mp = w & 3;          /* m strips 2mp, 2mp+1     */
    const int k0 = ks * KRANGE;

    /* stage A hi/lo: 128 rows x 16 float4 (=128 bf16) each */
    for (int idx = tid; idx < 2048; idx += 256) {
        int r = idx >> 4, c = idx & 15;
        size_t src = (size_t)(mt*128 + r)*XSTR + k0 + c*8;
        *(float4*)(sb + A_HI + r*RS + c*8) = *(const float4*)(g_xhi + src);
        *(float4*)(sb + A_LO + r*RS + c*8) = *(const float4*)(g_xlo + src);
    }
    /* stage B hi/lo: 160 rows x 16 float4 */
    for (int idx = tid; idx < 2560; idx += 256) {
        int r = idx >> 4, c = idx & 15;
        size_t src = (size_t)r*XSTR + k0 + c*8;
        *(float4*)(sb + B_HI + r*RS + c*8) = *(const float4*)(g_whi + src);
        *(float4*)(sb + B_LO + r*RS + c*8) = *(const float4*)(g_wlo + src);
    }
    __syncthreads();

    float acc[2][10][4];
#pragma unroll
    for (int s = 0; s < 2; s++)
#pragma unroll
        for (int t = 0; t < 10; t++)
#pragma unroll
            for (int r = 0; r < 4; r++) acc[s][t][r] = 0.f;

    const int aoffs[3] = {A_HI, A_HI, A_LO};
    const int boffs[3] = {B_HI, B_LO, B_HI};

#pragma unroll
    for (int p = 0; p < 3; p++) {
        const __nv_bfloat16* Ab = sb + aoffs[p] + (mp*32)*RS;
        const __nv_bfloat16* Bb = sb + boffs[p] + (nh*80 + g)*RS + tg*2;
#pragma unroll
        for (int kk = 0; kk < 8; kk++) {
            unsigned a[2][4];
#pragma unroll
            for (int s = 0; s < 2; s++) {
                const __nv_bfloat16* ap = Ab + s*16*RS + kk*16 + tg*2;
                a[s][0] = *(const unsigned*)(ap + g*RS);
                a[s][1] = *(const unsigned*)(ap + (g+8)*RS);
                a[s][2] = *(const unsigned*)(ap + g*RS + 8);
                a[s][3] = *(const unsigned*)(ap + (g+8)*RS + 8);
            }
#pragma unroll
            for (int t = 0; t < 10; t++) {
                const __nv_bfloat16* bp = Bb + t*8*RS + kk*16;
                unsigned b0 = *(const unsigned*)(bp);
                unsigned b1 = *(const unsigned*)(bp + 8);
                mma16816(acc[0][t], a[0], b0, b1);
                mma16816(acc[1][t], a[1], b0, b1);
            }
        }
    }

    /* epilogue: c0,c1 -> (row g, col 2tg..); c2,c3 -> (row g+8, ..) */
    float* base = g_pp + (size_t)ks*NB*NJD;
#pragma unroll
    for (int s = 0; s < 2; s++) {
        int m0 = mt*128 + (mp*2 + s)*16;
#pragma unroll
        for (int t = 0; t < 10; t++) {
            int jd = nh*80 + t*8 + tg*2;
            *(float2*)(base + (size_t)(m0+g)*NJD + jd)   = make_float2(acc[s][t][0], acc[s][t][1]);
            *(float2*)(base + (size_t)(m0+g+8)*NJD + jd) = make_float2(acc[s][t][2], acc[s][t][3]);
        }
    }
}

/* reduce KSPLIT partials + squash */
__global__ void k_reduce(float* __restrict__ outp, int to_out) {
    int tid = threadIdx.x;
    int g = tid >> 4, d = tid & 15;
    int bj = blockIdx.x*16 + g;
    int b = bj/10, j = bj - b*10;
    int idx = b*NJD + j*16 + d;
    float a0 = 0.f, a1 = 0.f, a2 = 0.f, a3 = 0.f;
#pragma unroll
    for (int k = 0; k < KSPLIT; k += 4) {
        a0 += g_pp[(size_t)(k+0)*NB*NJD + idx];
        a1 += g_pp[(size_t)(k+1)*NB*NJD + idx];
        a2 += g_pp[(size_t)(k+2)*NB*NJD + idx];
        a3 += g_pp[(size_t)(k+3)*NB*NJD + idx];
    }
    float v = (a0 + a1) + (a2 + a3);
    float ss = v*v;
    ss += __shfl_xor_sync(~0u, ss, 1);
    ss += __shfl_xor_sync(~0u, ss, 2);
    ss += __shfl_xor_sync(~0u, ss, 4);
    ss += __shfl_xor_sync(~0u, ss, 8);
    float f = sqrtf(ss)/(1.f + ss);
    float r = v*f;
    if (to_out) outp[idx] = r; else g_s[idx] = r;
}

/* ------------------------------------------------------------------ */
/* k_agree (round-4 proven): pl[half][i,j] via per-i A = x^T s, f32x2  */
/* ------------------------------------------------------------------ */
#define A_XOFF 0
#define A_SOFF 1024

__global__ __launch_bounds__(128,4) void k_agree(const float* __restrict__ x,
                                                 const float* __restrict__ W) {
    __shared__ __align__(16) float sm[11264];
    const int i0 = blockIdx.x*4;
    const int half = blockIdx.y;
    const int tid = threadIdx.x, il = tid >> 5, lane = tid & 31;

    u64 a[4][5];
#pragma unroll
    for (int dp2 = 0; dp2 < 4; dp2++)
#pragma unroll
        for (int k = 0; k < 5; k++) a[dp2][k] = 0ull;

    for (int bc = 0; bc < 4; bc++) {
        const int bb = half*128 + bc*32;
#pragma unroll
        for (int t = 0; t < 2; t++) {
            int q = tid + t*128;
            int bl = q >> 3, k = q & 7;
            *(float4*)(sm + A_XOFF + bl*32 + k*4) =
                *(const float4*)(x + (size_t)(bb+bl)*XSTR + i0*8 + k*4);
        }
#pragma unroll
        for (int t = 0; t < 20; t++) {
            int q = tid + t*128;
            int bl = q/80, m = q - bl*80;
            float2 sv = *(const float2*)(g_s + (size_t)(bb+bl)*NJD + m*2);
            *(float4*)(sm + A_SOFF + bl*320 + m*4) = make_float4(sv.x, sv.x, sv.y, sv.y);
        }
        __syncthreads();

#pragma unroll 4
        for (int bl = 0; bl < 32; bl++) {
            const float* xp = sm + A_XOFF + bl*32 + il*8;
            ulonglong2 x0 = *(const ulonglong2*)(xp);
            ulonglong2 x1 = *(const ulonglong2*)(xp + 4);
            u64 xv[4] = {x0.x, x0.y, x1.x, x1.y};
            const float* sp = sm + A_SOFF + bl*320;
#pragma unroll
            for (int k = 0; k < 5; k++) {
                u64 sv = *(const u64*)(sp + (lane + 32*k)*2);
#pragma unroll
                for (int dp2 = 0; dp2 < 4; dp2++) fma2(a[dp2][k], xv[dp2], sv);
            }
        }
        __syncthreads();
    }

#pragma unroll
    for (int dp2 = 0; dp2 < 4; dp2++)
#pragma unroll
        for (int k = 0; k < 5; k++)
            *(u64*)(sm + il*1280 + (lane + 32*k)*8 + dp2*2) = a[dp2][k];
    __syncthreads();

    if (tid < 40) {
        int iloc = tid/10, jj = tid - iloc*10;
        int i = i0 + iloc;
        const float* Wi = W  + (size_t)i*WSTR + jj*128;
        const float* Ai = sm + iloc*1280 + jj*128;
        float accv = 0.f;
#pragma unroll
        for (int t = 0; t < 32; t++) {
            float4 wv = *(const float4*)(Wi + t*4);
            float4 av = *(const float4*)(Ai + t*4);
            accv += wv.x*av.x + wv.y*av.y + wv.z*av.z + wv.w*av.w;
        }
        g_pl[half][i*NJ + jj] = accv;
    }
}

extern "C" void kernel_launch(void* const* d_in, const int* in_sizes, int n_in,
                              void* d_out, int out_size) {
    const float* x = (const float*)d_in[0];
    const float* W = (const float*)d_in[1];
    float* out = (float*)d_out;

    static int smem_set = 0;
    if (!smem_set) {
        cudaFuncSetAttribute(k_gemm, cudaFuncAttributeMaxDynamicSharedMemorySize, GEMM_SMEM);
        smem_set = 1;
    }

    k_splitx<<<2304, 256>>>(x);
    k_zero<<<45, 256>>>();
    for (int it = 0; it < 3; it++) {
        k_softmax<<<9, 128>>>(it ? 1 : 0);
        k_buildB<<<1440, 256>>>(W);
        k_gemm<<<dim3(2, KSPLIT), 256, GEMM_SMEM>>>();
        k_reduce<<<160, 256>>>(out, (it == 2) ? 1 : 0);
        if (it < 2) k_agree<<<dim3(288, 2), 128>>>(x, W);
    }
}

// round 7
// speedup vs baseline: 2.9214x; 1.2587x over previous
#include <cuda_runtime.h>
#include <cuda_bf16.h>
#include <math.h>
#include <stdint.h>

#define NB 256
#define NI 1152
#define NJ 10
#define NJD 160
#define XSTR 9216
#define KSPLIT 72

__device__ float g_pp[KSPLIT*NB*NJD];
__device__ float g_plb[2][2][NI*NJ];             /* [iter][kchunk][i*10+j] */
__device__ __nv_bfloat16 g_xhi[NB*XSTR];         /* [b][m]  */
__device__ __nv_bfloat16 g_xlo[NB*XSTR];
__device__ __nv_bfloat16 g_xthi[XSTR*NB];        /* [m][b]  */
__device__ __nv_bfloat16 g_xtlo[XSTR*NB];
__device__ __nv_bfloat16 g_sthi[NJD*NB];         /* [jd][b] */
__device__ __nv_bfloat16 g_stlo[NJD*NB];

__device__ __forceinline__ void mma16816(float* c, const unsigned* a,
                                         unsigned b0, unsigned b1) {
    asm volatile("mma.sync.aligned.m16n8k16.row.col.f32.bf16.bf16.f32 "
                 "{%0,%1,%2,%3}, {%4,%5,%6,%7}, {%8,%9}, {%0,%1,%2,%3};"
                 : "+f"(c[0]), "+f"(c[1]), "+f"(c[2]), "+f"(c[3])
                 : "r"(a[0]), "r"(a[1]), "r"(a[2]), "r"(a[3]), "r"(b0), "r"(b1));
}
__device__ __forceinline__ void split_bf(float v, __nv_bfloat16& h, __nv_bfloat16& l) {
    h = __float2bfloat16_rn(v);
    l = __float2bfloat16_rn(v - __bfloat162float(h));
}

/* split x into bf16 hi/lo, layout [b][m] (once) */
__global__ void k_splitx(const float* __restrict__ x) {
    int e = blockIdx.x*256 + threadIdx.x;
    float4 v = *(const float4*)(x + (size_t)e*4);
    __nv_bfloat16 h0,h1,h2,h3,l0,l1,l2,l3;
    split_bf(v.x,h0,l0); split_bf(v.y,h1,l1); split_bf(v.z,h2,l2); split_bf(v.w,h3,l3);
    __nv_bfloat162* ph = (__nv_bfloat162*)(g_xhi + (size_t)e*4);
    __nv_bfloat162* pl = (__nv_bfloat162*)(g_xlo + (size_t)e*4);
    ph[0] = __nv_bfloat162(h0,h1); ph[1] = __nv_bfloat162(h2,h3);
    pl[0] = __nv_bfloat162(l0,l1); pl[1] = __nv_bfloat162(l2,l3);
}

/* transpose x -> xt [m][b] hi/lo (once) */
__global__ void k_xt(const float* __restrict__ x) {
    __shared__ float s[32][33];
    const int m0 = blockIdx.x*32, b0 = blockIdx.y*32;
    const int tid = threadIdx.x, tm = tid & 31, tr = tid >> 5;
#pragma unroll
    for (int q = 0; q < 4; q++) {
        int bl = tr + q*8;
        s[bl][tm] = x[(size_t)(b0+bl)*XSTR + m0 + tm];
    }
    __syncthreads();
#pragma unroll
    for (int q = 0; q < 4; q++) {
        int ml = tr + q*8;
        float v = s[tm][ml];
        __nv_bfloat16 h, l; split_bf(v, h, l);
        size_t o = (size_t)(m0+ml)*NB + b0 + tm;
        g_xthi[o] = h; g_xtlo[o] = l;
    }
}

/* ------------------------------------------------------------------ */
/* k_gemm: pp[ks][b][jd] = sum_{k in slice} x[b,k] * (c(.)W)[jd,k]     */
/* softmax (from plb sums) + B build (c*W split) fused in prologue.    */
/* grid (2 mtiles, 72 kslices) x 256 thr.                              */
/* ------------------------------------------------------------------ */
#define RS 136
#define A_HI 0
#define A_LO (128*RS)
#define B_HI (2*128*RS)
#define B_LO (2*128*RS + 160*RS)
#define GEMM_SMEM ((2*128*RS + 2*160*RS) * 2)

__global__ __launch_bounds__(256,1) void k_gemm(const float* __restrict__ W, int it) {
    extern __shared__ __align__(16) __nv_bfloat16 sb[];
    __shared__ float c_sm[160];
    const int mt = blockIdx.x, ks = blockIdx.y;
    const int tid = threadIdx.x, w = tid >> 5, lane = tid & 31;
    const int g = lane >> 2, tg = lane & 3;
    const int nh = w >> 2, mp = w & 3;
    const int k0 = ks*128, i0 = ks*16;

    /* fused softmax: logits(i,j) = sum over previous iters of pl parts */
    if (tid < 16) {
        int i = i0 + tid;
        float l[NJ];
        float m = -1e30f;
#pragma unroll
        for (int j = 0; j < NJ; j++) {
            float v = 0.f;
            for (int t = 0; t < it; t++)
                v += g_plb[t][0][i*NJ+j] + g_plb[t][1][i*NJ+j];
            l[j] = v; m = fmaxf(m, v);
        }
        float ssum = 0.f;
#pragma unroll
        for (int j = 0; j < NJ; j++) { l[j] = expf(l[j]-m); ssum += l[j]; }
        float inv = 1.f/ssum;
#pragma unroll
        for (int j = 0; j < NJ; j++) c_sm[tid*NJ + j] = l[j]*inv;
    }
    __syncthreads();

    /* stage A hi/lo: 128 b-rows x 128 k */
    for (int idx = tid; idx < 2048; idx += 256) {
        int r = idx >> 4, c4 = idx & 15;
        size_t src = (size_t)(mt*128 + r)*XSTR + k0 + c4*8;
        *(float4*)(sb + A_HI + r*RS + c4*8) = *(const float4*)(g_xhi + src);
        *(float4*)(sb + A_LO + r*RS + c4*8) = *(const float4*)(g_xlo + src);
    }
    /* build B = c (.) W, split hi/lo: 160 jd-rows x 128 k (k = il*8+dp) */
    for (int idx = tid; idx < 5120; idx += 256) {
        int il = idx / 320, rem = idx - il*320;
        int j = rem >> 5, r2 = rem & 31, d = r2 >> 1, dph = r2 & 1;
        float4 wv = *(const float4*)(W + (size_t)(i0+il)*1280 + j*128 + d*8 + dph*4);
        float c = c_sm[il*NJ + j];
        wv.x *= c; wv.y *= c; wv.z *= c; wv.w *= c;
        __nv_bfloat16 h0,h1,h2,h3,l0,l1,l2,l3;
        split_bf(wv.x,h0,l0); split_bf(wv.y,h1,l1); split_bf(wv.z,h2,l2); split_bf(wv.w,h3,l3);
        int off = (j*16 + d)*RS + il*8 + dph*4;
        *(__nv_bfloat162*)(sb + B_HI + off)     = __nv_bfloat162(h0,h1);
        *(__nv_bfloat162*)(sb + B_HI + off + 2) = __nv_bfloat162(h2,h3);
        *(__nv_bfloat162*)(sb + B_LO + off)     = __nv_bfloat162(l0,l1);
        *(__nv_bfloat162*)(sb + B_LO + off + 2) = __nv_bfloat162(l2,l3);
    }
    __syncthreads();

    float acc[2][10][4];
#pragma unroll
    for (int s = 0; s < 2; s++)
#pragma unroll
        for (int t = 0; t < 10; t++)
#pragma unroll
            for (int r = 0; r < 4; r++) acc[s][t][r] = 0.f;

    const int aoffs[3] = {A_HI, A_HI, A_LO};
    const int boffs[3] = {B_HI, B_LO, B_HI};
#pragma unroll
    for (int p = 0; p < 3; p++) {
        const __nv_bfloat16* Ab = sb + aoffs[p] + (mp*32)*RS;
        const __nv_bfloat16* Bb = sb + boffs[p] + (nh*80 + g)*RS + tg*2;
#pragma unroll
        for (int kk = 0; kk < 8; kk++) {
            unsigned a[2][4];
#pragma unroll
            for (int s = 0; s < 2; s++) {
                const __nv_bfloat16* ap = Ab + s*16*RS + kk*16 + tg*2;
                a[s][0] = *(const unsigned*)(ap + g*RS);
                a[s][1] = *(const unsigned*)(ap + (g+8)*RS);
                a[s][2] = *(const unsigned*)(ap + g*RS + 8);
                a[s][3] = *(const unsigned*)(ap + (g+8)*RS + 8);
            }
#pragma unroll
            for (int t = 0; t < 10; t++) {
                const __nv_bfloat16* bp = Bb + t*8*RS + kk*16;
                unsigned b0 = *(const unsigned*)(bp);
                unsigned b1 = *(const unsigned*)(bp + 8);
                mma16816(acc[0][t], a[0], b0, b1);
                mma16816(acc[1][t], a[1], b0, b1);
            }
        }
    }

    float* base = g_pp + (size_t)ks*NB*NJD;
#pragma unroll
    for (int s = 0; s < 2; s++) {
        int m0 = mt*128 + (mp*2 + s)*16;
#pragma unroll
        for (int t = 0; t < 10; t++) {
            int jd = nh*80 + t*8 + tg*2;
            *(float2*)(base + (size_t)(m0+g)*NJD + jd)   = make_float2(acc[s][t][0], acc[s][t][1]);
            *(float2*)(base + (size_t)(m0+g+8)*NJD + jd) = make_float2(acc[s][t][2], acc[s][t][3]);
        }
    }
}

/* reduce 72 partials + squash; emit s transposed hi/lo (or final out) */
__global__ void k_reduce(float* __restrict__ outp, int final_it) {
    __shared__ unsigned short sh[256], sl[256];
    const int tid = threadIdx.x;
    const int tb = tid >> 4, d = tid & 15;
    const int b = blockIdx.x*16 + tb, j = blockIdx.y;
    const int idx = b*NJD + j*16 + d;
    float a0=0.f, a1=0.f, a2=0.f, a3=0.f;
#pragma unroll
    for (int k = 0; k < KSPLIT; k += 4) {
        a0 += g_pp[(size_t)(k+0)*NB*NJD + idx];
        a1 += g_pp[(size_t)(k+1)*NB*NJD + idx];
        a2 += g_pp[(size_t)(k+2)*NB*NJD + idx];
        a3 += g_pp[(size_t)(k+3)*NB*NJD + idx];
    }
    float v = (a0+a1) + (a2+a3);
    float ss = v*v;
    ss += __shfl_xor_sync(~0u, ss, 1);
    ss += __shfl_xor_sync(~0u, ss, 2);
    ss += __shfl_xor_sync(~0u, ss, 4);
    ss += __shfl_xor_sync(~0u, ss, 8);
    float f = sqrtf(ss)/(1.f + ss);
    float r = v*f;
    if (final_it) { outp[idx] = r; return; }
    __nv_bfloat16 h, l; split_bf(r, h, l);
    sh[d*16 + tb] = *(unsigned short*)&h;
    sl[d*16 + tb] = *(unsigned short*)&l;
    __syncthreads();
    int d2 = tid >> 4, tb2 = tid & 15;
    size_t o = (size_t)(j*16 + d2)*NB + blockIdx.x*16 + tb2;
    ((unsigned short*)g_sthi)[o] = sh[tid];
    ((unsigned short*)g_stlo)[o] = sl[tid];
}

/* ------------------------------------------------------------------ */
/* k_agree: Amat[m][jd] = sum_{b chunk} xt[m][b] st[jd][b]  (HMMA),    */
/* then pl[it][kc][i,j] = sum_{d,dp} W[i,j,d,dp] Amat[i*8+dp][j*16+d]. */
/* grid (72 mtiles, 2 kchunks) x 256 thr.                              */
/* ------------------------------------------------------------------ */
__global__ __launch_bounds__(256,1) void k_agree(const float* __restrict__ W, int it) {
    extern __shared__ __align__(16) __nv_bfloat16 sb[];
    const int a_ = blockIdx.x, kc = blockIdx.y;
    const int tid = threadIdx.x, w = tid >> 5, lane = tid & 31;
    const int g = lane >> 2, tg = lane & 3;
    const int nh = w >> 2, mp = w & 3;

    /* stage A (xt) hi/lo: 128 m-rows x 128 b */
    for (int idx = tid; idx < 2048; idx += 256) {
        int r = idx >> 4, c4 = idx & 15;
        size_t src = (size_t)(a_*128 + r)*NB + kc*128 + c4*8;
        *(float4*)(sb + A_HI + r*RS + c4*8) = *(const float4*)(g_xthi + src);
        *(float4*)(sb + A_LO + r*RS + c4*8) = *(const float4*)(g_xtlo + src);
    }
    /* stage B (st) hi/lo: 160 jd-rows x 128 b */
    for (int idx = tid; idx < 2560; idx += 256) {
        int r = idx >> 4, c4 = idx & 15;
        size_t src = (size_t)r*NB + kc*128 + c4*8;
        *(float4*)(sb + B_HI + r*RS + c4*8) = *(const float4*)(g_sthi + src);
        *(float4*)(sb + B_LO + r*RS + c4*8) = *(const float4*)(g_stlo + src);
    }
    __syncthreads();

    float acc[2][10][4];
#pragma unroll
    for (int s = 0; s < 2; s++)
#pragma unroll
        for (int t = 0; t < 10; t++)
#pragma unroll
            for (int r = 0; r < 4; r++) acc[s][t][r] = 0.f;

    const int aoffs[3] = {A_HI, A_HI, A_LO};
    const int boffs[3] = {B_HI, B_LO, B_HI};
#pragma unroll
    for (int p = 0; p < 3; p++) {
        const __nv_bfloat16* Ab = sb + aoffs[p] + (mp*32)*RS;
        const __nv_bfloat16* Bb = sb + boffs[p] + (nh*80 + g)*RS + tg*2;
#pragma unroll
        for (int kk = 0; kk < 8; kk++) {
            unsigned a[2][4];
#pragma unroll
            for (int s = 0; s < 2; s++) {
                const __nv_bfloat16* ap = Ab + s*16*RS + kk*16 + tg*2;
                a[s][0] = *(const unsigned*)(ap + g*RS);
                a[s][1] = *(const unsigned*)(ap + (g+8)*RS);
                a[s][2] = *(const unsigned*)(ap + g*RS + 8);
                a[s][3] = *(const unsigned*)(ap + (g+8)*RS + 8);
            }
#pragma unroll
            for (int t = 0; t < 10; t++) {
                const __nv_bfloat16* bp = Bb + t*8*RS + kk*16;
                unsigned b0 = *(const unsigned*)(bp);
                unsigned b1 = *(const unsigned*)(bp + 8);
                mma16816(acc[0][t], a[0], b0, b1);
                mma16816(acc[1][t], a[1], b0, b1);
            }
        }
    }
    __syncthreads();                 /* staging dead; reuse smem as Amat f32 */

    float* At = (float*)sb;          /* [128][160] */
#pragma unroll
    for (int s = 0; s < 2; s++) {
        int m0 = (mp*2 + s)*16;
#pragma unroll
        for (int t = 0; t < 10; t++) {
            int jd = nh*80 + t*8 + tg*2;
            *(float2*)(At + (m0+g)*NJD + jd)   = make_float2(acc[s][t][0], acc[s][t][1]);
            *(float2*)(At + (m0+g+8)*NJD + jd) = make_float2(acc[s][t][2], acc[s][t][3]);
        }
    }
    __syncthreads();

    if (tid < 160) {
        int il = tid / NJ, j = tid - il*NJ;
        int i = a_*16 + il;
        float accv = 0.f;
#pragma unroll
        for (int d = 0; d < 16; d++) {
            float4 w0 = *(const float4*)(W + (size_t)i*1280 + j*128 + d*8);
            float4 w1 = *(const float4*)(W + (size_t)i*1280 + j*128 + d*8 + 4);
            const float* ap = At + (il*8)*NJD + j*16 + d;
            accv += w0.x*ap[0*NJD] + w0.y*ap[1*NJD] + w0.z*ap[2*NJD] + w0.w*ap[3*NJD]
                  + w1.x*ap[4*NJD] + w1.y*ap[5*NJD] + w1.z*ap[6*NJD] + w1.w*ap[7*NJD];
        }
        g_plb[it][kc][i*NJ + j] = accv;
    }
}

extern "C" void kernel_launch(void* const* d_in, const int* in_sizes, int n_in,
                              void* d_out, int out_size) {
    const float* x = (const float*)d_in[0];
    const float* W = (const float*)d_in[1];
    float* out = (float*)d_out;

    cudaFuncSetAttribute(k_gemm,  cudaFuncAttributeMaxDynamicSharedMemorySize, GEMM_SMEM);
    cudaFuncSetAttribute(k_agree, cudaFuncAttributeMaxDynamicSharedMemorySize, GEMM_SMEM);

    k_splitx<<<2304, 256>>>(x);
    k_xt<<<dim3(288, 8), 256>>>(x);
    for (int it = 0; it < 3; it++) {
        k_gemm<<<dim3(2, KSPLIT), 256, GEMM_SMEM>>>(W, it);
        k_reduce<<<dim3(16, NJ), 256>>>(out, (it == 2) ? 1 : 0);
        if (it < 2) k_agree<<<dim3(72, 2), 256, GEMM_SMEM>>>(W, it);
    }
}